// round 13
// baseline (speedup 1.0000x reference)
#include <cuda_runtime.h>
#include <cuda_bf16.h>
#include <cstdint>

// Problem constants
#define B_    256
#define NMAX_ 512
#define H_    256
#define C_    64
#define HID_  512
#define NEGV  (-1000000000.0f)

// GEMM tiling: CTA 128M x 256N, KC=64 bf16, mma m16n8k16
#define CTA_M 128
#define CTA_N 256
#define KC    64
#define ROWB  144                    // 64 bf16 = 128B + 16B pad
#define A_STAGE (CTA_M * ROWB)       // 18432
#define B_STAGE (CTA_N * ROWB)       // 36864
#define STAGE   (A_STAGE + B_STAGE)  // 55296
#define NSTAGE  3
#define SMEM_BYTES (NSTAGE * STAGE)  // 165888

#define NPERS   152                  // persistent CTAs (GB300: 152 SMs)

// ---- device scratch (allocation-free rule) ----
__device__ float g_base[B_ * HID_];
__device__ float g_scores[B_ * NMAX_];
__device__ __nv_bfloat16 g_nodes_b[(size_t)B_ * NMAX_ * H_];    // 67MB
__device__ __nv_bfloat16 g_h1b[(size_t)B_ * NMAX_ * HID_];      // 134MB
__device__ __nv_bfloat16 g_w1b[2][HID_][H_];   // [variant][n][k]
__device__ __nv_bfloat16 g_w2b[HID_][HID_];    // [n][k]
__device__ int g_ctr;                 // work-queue counter
__device__ int g_ready[B_ * 4];       // per (b, rt): # layer-1 halves done

// ---- helpers ----
__device__ __forceinline__ uint32_t smem_u32(const void* p) {
    uint32_t a;
    asm("{ .reg .u64 t; cvta.to.shared.u64 t, %1; cvt.u32.u64 %0, t; }"
        : "=r"(a) : "l"(p));
    return a;
}
__device__ __forceinline__ void cp16(uint32_t s, const void* g) {
    asm volatile("cp.async.cg.shared.global [%0], [%1], 16;"
                 :: "r"(s), "l"(g) : "memory");
}
__device__ __forceinline__ void ldsm4(uint32_t addr, uint32_t* r) {
    asm volatile("ldmatrix.sync.aligned.m8n8.x4.shared.b16 {%0,%1,%2,%3}, [%4];"
                 : "=r"(r[0]), "=r"(r[1]), "=r"(r[2]), "=r"(r[3]) : "r"(addr));
}
__device__ __forceinline__ void mma16816(float* c, const uint32_t* a,
                                         uint32_t b0, uint32_t b1) {
    asm volatile(
        "mma.sync.aligned.m16n8k16.row.col.f32.bf16.bf16.f32 "
        "{%0,%1,%2,%3}, {%4,%5,%6,%7}, {%8,%9}, {%0,%1,%2,%3};"
        : "+f"(c[0]), "+f"(c[1]), "+f"(c[2]), "+f"(c[3])
        : "r"(a[0]), "r"(a[1]), "r"(a[2]), "r"(a[3]), "r"(b0), "r"(b1));
}
__device__ __forceinline__ uint32_t packbf(float lo, float hi) {
    __nv_bfloat162 v = __floats2bfloat162_rn(lo, hi);
    return *(uint32_t*)&v;
}

// ============================================================
// Fused prep kernel (also zeroes queue counter + ready flags)
// ============================================================
#define PREP_BLOCKS 3328
__global__ void __launch_bounds__(256) prep_kernel(
    const float* __restrict__ nodes,
    const float* __restrict__ cc,
    const float* __restrict__ W1,
    const float* __restrict__ b1,
    const float* __restrict__ W2,
    const int* __restrict__ dirns,
    const int* __restrict__ ncnt) {
    int blk = blockIdx.x;
    int t = threadIdx.x;
    if (blk < 256) {
        __shared__ float sS[H_];
        __shared__ float sC[C_];
        int b = blk;
        int nc = ncnt[b];
        const float* src = nodes + ((size_t)b * NMAX_ + (size_t)(nc - 1)) * H_;
        sS[t] = src[t];
        if (t < C_) sC[t] = cc[b * C_ + t];
        __syncthreads();
        int off_src = (dirns[b] == 1) ? H_ : 0;
        int j = t;
        float a0 = b1[j], a1 = b1[j + 256];
        const float* Wp = W1 + (size_t)off_src * HID_;
#pragma unroll 8
        for (int k = 0; k < H_; k++) {
            float s = sS[k];
            a0 = fmaf(s, Wp[(size_t)k * HID_ + j], a0);
            a1 = fmaf(s, Wp[(size_t)k * HID_ + j + 256], a1);
        }
        const float* Wc = W1 + (size_t)(2 * H_) * HID_;
#pragma unroll 8
        for (int k = 0; k < C_; k++) {
            float s = sC[k];
            a0 = fmaf(s, Wc[(size_t)k * HID_ + j], a0);
            a1 = fmaf(s, Wc[(size_t)k * HID_ + j + 256], a1);
        }
        g_base[b * HID_ + j] = a0;
        g_base[b * HID_ + j + 256] = a1;
    } else if (blk < 2304) {
        // nodes fp32 -> bf16; dead candidate rows skipped
        const float2* src = (const float2*)nodes;
        uint32_t* dst = (uint32_t*)g_nodes_b;
        int idx = (blk - 256) * 256 + t;
        const int STRIDE = 2048 * 256;
        const int TOTAL = B_ * NMAX_ * (H_ / 2);  // 16777216
#pragma unroll 2
        for (int p = idx; p < TOTAL; p += STRIDE) {
            int grow = p >> 7;
            int b = grow >> 9, d = grow & 511;
            if (d >= ncnt[b] - 1) continue;
            float2 v = src[p];
            dst[p] = packbf(v.x, v.y);
        }
    } else if (blk < 2560) {
        // W1 slice [256k][512n] -> g_w1b[v][n][k] bf16, 32x32 tiles
        __shared__ float s[32][33];
        int u = blk - 2304;
        int v = u >> 7;
        u &= 127;
        int k0 = (u >> 4) * 32, n0 = (u & 15) * 32;
        int tx = t & 31, ty = t >> 5;
#pragma unroll
        for (int i = 0; i < 4; i++)
            s[ty + 8 * i][tx] =
                W1[(size_t)(v * 256 + k0 + ty + 8 * i) * HID_ + n0 + tx];
        __syncthreads();
        int n = t & 31, kp0 = t >> 5;
#pragma unroll
        for (int i = 0; i < 2; i++) {
            int kp = kp0 + 8 * i;
            uint32_t w = packbf(s[2 * kp][n], s[2 * kp + 1][n]);
            ((uint32_t*)&g_w1b[v][n0 + n][0])[(k0 >> 1) + kp] = w;
        }
    } else if (blk < 2816) {
        // W2 -> g_w2b[n][k]
        __shared__ float s[32][33];
        int u = blk - 2560;
        int k0 = (u >> 4) * 32, n0 = (u & 15) * 32;
        int tx = t & 31, ty = t >> 5;
#pragma unroll
        for (int i = 0; i < 4; i++)
            s[ty + 8 * i][tx] = W2[(size_t)(k0 + ty + 8 * i) * HID_ + n0 + tx];
        __syncthreads();
        int n = t & 31, kp0 = t >> 5;
#pragma unroll
        for (int i = 0; i < 2; i++) {
            int kp = kp0 + 8 * i;
            uint32_t w = packbf(s[2 * kp][n], s[2 * kp + 1][n]);
            ((uint32_t*)&g_w2b[n0 + n][0])[(k0 >> 1) + kp] = w;
        }
    } else {
        int z = blk - 2816;
        g_scores[z * 256 + t] = 0.f;
        if (z < 4) g_ready[z * 256 + t] = 0;
        if (z == 4 && t == 0) g_ctr = 0;
    }
}

// ============================================================
// One GEMM tile (layer templated). Returns after epilogue.
// ============================================================
template <int LAYER>
__device__ __forceinline__ void gemm_tile(
    uint32_t smb, int t, int b, int rt, int nt,
    const int* __restrict__ dirns,
    const float* __restrict__ b2v,
    const float* __restrict__ W3v) {
    const int d0 = rt * CTA_M, j0 = nt * CTA_N;
    constexpr int K = (LAYER == 1) ? 256 : 512;
    constexpr int NC = K / KC;

    const __nv_bfloat16* Asrc;
    const __nv_bfloat16* Bsrc;
    if (LAYER == 1) {
        Asrc = g_nodes_b + ((size_t)b * NMAX_ + d0) * H_;
        Bsrc = &g_w1b[(dirns[b] == 1) ? 0 : 1][j0][0];
    } else {
        Asrc = g_h1b + ((size_t)b * NMAX_ + d0) * HID_;
        Bsrc = &g_w2b[j0][0];
    }

    auto load_chunk = [&](int c, int stage) {
        uint32_t sA = smb + stage * STAGE;
        uint32_t sB = sA + A_STAGE;
#pragma unroll
        for (int j = 0; j < 2; j++) {
            int i = t + j * 512;
            int row = i >> 3, q = i & 7;
            const char* g = (const char*)(Asrc + (size_t)row * K + c * KC) + q * 16;
            cp16(sA + row * ROWB + q * 16, g);
        }
#pragma unroll
        for (int j = 0; j < 4; j++) {
            int i = t + j * 512;
            int row = i >> 3, q = i & 7;
            const char* g = (const char*)(Bsrc + (size_t)row * K + c * KC) + q * 16;
            cp16(sB + row * ROWB + q * 16, g);
        }
        asm volatile("cp.async.commit_group;" ::: "memory");
    };

    load_chunk(0, 0);
    load_chunk(1, 1);

    const int l = t & 31, w = t >> 5, wm = w >> 2, wn = w & 3;
    const uint32_t a_lane =
        (uint32_t)((wm * 32 + (l & 15)) * ROWB + (l >> 4) * 16);
    const uint32_t b_lane =
        (uint32_t)((wn * 64 + (l & 15)) * ROWB + (l >> 4) * 16);

    float cacc[2][8][4];
#pragma unroll
    for (int i = 0; i < 2; i++)
#pragma unroll
        for (int j = 0; j < 8; j++)
#pragma unroll
            for (int q = 0; q < 4; q++) cacc[i][j][q] = 0.f;

    for (int c = 0; c < NC; c++) {
        asm volatile("cp.async.wait_group 1;" ::: "memory");
        __syncthreads();
        if (c + 2 < NC)
            load_chunk(c + 2, (c + 2) % NSTAGE);
        else
            asm volatile("cp.async.commit_group;" ::: "memory");

        const int st = c % NSTAGE;
        const uint32_t sA = smb + st * STAGE, sB = sA + A_STAGE;
#pragma unroll
        for (int ks = 0; ks < 4; ks++) {
            uint32_t a[2][4];
#pragma unroll
            for (int mi = 0; mi < 2; mi++)
                ldsm4(sA + a_lane + mi * 16 * ROWB + ks * 32, a[mi]);
#pragma unroll
            for (int nbp = 0; nbp < 4; nbp++) {
                uint32_t bq[4];
                ldsm4(sB + b_lane + nbp * 16 * ROWB + ks * 32, bq);
#pragma unroll
                for (int mi = 0; mi < 2; mi++) {
                    mma16816(cacc[mi][nbp * 2],     a[mi], bq[0], bq[2]);
                    mma16816(cacc[mi][nbp * 2 + 1], a[mi], bq[1], bq[3]);
                }
            }
        }
    }
    // drain our own outstanding groups so next tile's cp.async stages are clean
    asm volatile("cp.async.wait_group 0;" ::: "memory");

    const int lrow = d0 + wm * 32 + (l >> 2);
    const int lcol0 = j0 + wn * 64 + (l & 3) * 2;
    if (LAYER == 1) {
#pragma unroll
        for (int mi = 0; mi < 2; mi++) {
            int r0 = lrow + mi * 16, r1 = r0 + 8;
#pragma unroll
            for (int nj = 0; nj < 8; nj++) {
                int col = lcol0 + nj * 8;
                float2 bs = *(const float2*)&g_base[b * HID_ + col];
                uint32_t v0 = packbf(fmaxf(cacc[mi][nj][0] + bs.x, 0.f),
                                     fmaxf(cacc[mi][nj][1] + bs.y, 0.f));
                uint32_t v1 = packbf(fmaxf(cacc[mi][nj][2] + bs.x, 0.f),
                                     fmaxf(cacc[mi][nj][3] + bs.y, 0.f));
                ((uint32_t*)g_h1b)[(((size_t)b * NMAX_ + r0) * HID_ + col) >> 1] = v0;
                ((uint32_t*)g_h1b)[(((size_t)b * NMAX_ + r1) * HID_ + col) >> 1] = v1;
            }
        }
        // release: all stores visible, then bump ready flag
        __syncthreads();
        if (t == 0) {
            __threadfence();
            atomicAdd(&g_ready[b * 4 + rt], 1);
        }
    } else {
        float s[2][2] = {{0.f, 0.f}, {0.f, 0.f}};
#pragma unroll
        for (int mi = 0; mi < 2; mi++)
#pragma unroll
            for (int nj = 0; nj < 8; nj++) {
                int col = lcol0 + nj * 8;
                float2 bb = *(const float2*)&b2v[col];
                float2 ww = *(const float2*)&W3v[col];
                s[mi][0] += fmaxf(cacc[mi][nj][0] + bb.x, 0.f) * ww.x +
                            fmaxf(cacc[mi][nj][1] + bb.y, 0.f) * ww.y;
                s[mi][1] += fmaxf(cacc[mi][nj][2] + bb.x, 0.f) * ww.x +
                            fmaxf(cacc[mi][nj][3] + bb.y, 0.f) * ww.y;
            }
#pragma unroll
        for (int mi = 0; mi < 2; mi++)
#pragma unroll
            for (int h = 0; h < 2; h++) {
                float v = s[mi][h];
                v += __shfl_xor_sync(0xffffffffu, v, 1);
                v += __shfl_xor_sync(0xffffffffu, v, 2);
                if ((l & 3) == 0)
                    atomicAdd(&g_scores[b * NMAX_ + lrow + mi * 16 + h * 8], v);
            }
    }
}

// ============================================================
// Persistent fused GEMM: work queue over both layers.
// ids [0,2048): layer1 (b fastest); [2048,4096): layer2.
// All layer-1 ids are dequeued before any layer-2 id (monotonic
// counter), so a layer-2 spin always has its producers running
// or done -> no deadlock.
// ============================================================
__global__ void __launch_bounds__(512) fused_gemm_kernel(
    const int* __restrict__ dirns,
    const int* __restrict__ ncnt,
    const float* __restrict__ b2v,
    const float* __restrict__ W3v) {
    extern __shared__ char smdyn[];
    const uint32_t smb = smem_u32(smdyn);
    const int t = threadIdx.x;
    __shared__ int sh_id;

    for (;;) {
        if (t == 0) sh_id = atomicAdd(&g_ctr, 1);
        __syncthreads();
        const int id = sh_id;
        __syncthreads();
        if (id >= 4096) break;

        const int layer = id >> 11;
        const int rem = id & 2047;
        const int b = rem & 255;
        const int u = rem >> 8;      // 0..7
        const int rt = u >> 1, nt = u & 1;

        if (rt * CTA_M >= ncnt[b] - 1) continue;  // dead tile

        if (layer == 0) {
            gemm_tile<1>(smb, t, b, rt, nt, dirns, b2v, W3v);
        } else {
            if (t == 0) {
                int v;
                do {
                    asm volatile("ld.acquire.gpu.global.b32 %0, [%1];"
                                 : "=r"(v) : "l"(&g_ready[b * 4 + rt]) : "memory");
                } while (v < 2);
            }
            __syncthreads();
            gemm_tile<2>(smb, t, b, rt, nt, dirns, b2v, W3v);
        }
    }
}

// ============================================================
// loss: masked log-softmax -> per-batch loss (b3 cancels)
// ============================================================
__global__ void loss_kernel(const int* __restrict__ ncnt,
                            const int* __restrict__ dests,
                            float* __restrict__ out) {
    __shared__ float red[256];
    int b = blockIdx.x, t = threadIdx.x;
    int lim = ncnt[b] - 1;
    const float* sc = g_scores + b * NMAX_;
    float s1 = (t < lim) ? sc[t] : NEGV;
    int d2 = t + 256;
    float s2 = (d2 < lim) ? sc[d2] : NEGV;

    float m = fmaxf(s1, s2);
    red[t] = m;
    __syncthreads();
    for (int o = 128; o; o >>= 1) {
        if (t < o) red[t] = fmaxf(red[t], red[t + o]);
        __syncthreads();
    }
    float mx = red[0];
    __syncthreads();
    float e = expf(s1 - mx) + expf(s2 - mx);
    red[t] = e;
    __syncthreads();
    for (int o = 128; o; o >>= 1) {
        if (t < o) red[t] += red[t + o];
        __syncthreads();
    }
    if (t == 0) {
        float lse = mx + logf(red[0]);
        out[b] = lse - sc[dests[b]];
    }
}

// ============================================================
extern "C" void kernel_launch(void* const* d_in, const int* in_sizes, int n_in,
                              void* d_out, int out_size) {
    const float* nodes = (const float*)d_in[0];
    const float* cc    = (const float*)d_in[1];
    const float* W1    = (const float*)d_in[2];
    const float* b1    = (const float*)d_in[3];
    const float* W2    = (const float*)d_in[4];
    const float* b2    = (const float*)d_in[5];
    const float* W3    = (const float*)d_in[6];
    // d_in[7] = b3 (cancels in log_softmax)
    const int* dirns   = (const int*)d_in[8];
    const int* ncnt    = (const int*)d_in[9];
    const int* dests   = (const int*)d_in[10];
    float* out = (float*)d_out;

    cudaFuncSetAttribute(fused_gemm_kernel,
                         cudaFuncAttributeMaxDynamicSharedMemorySize, SMEM_BYTES);

    prep_kernel<<<PREP_BLOCKS, 256>>>(nodes, cc, W1, b1, W2, dirns, ncnt);
    fused_gemm_kernel<<<NPERS, 512, SMEM_BYTES>>>(dirns, ncnt, b2, W3);
    loss_kernel<<<B_, 256>>>(ncnt, dests, out);
}